// round 3
// baseline (speedup 1.0000x reference)
#include <cuda_runtime.h>

// Problem constants
#define NBATCH 32
#define NCHAN  3
#define NIMG   (NBATCH * NCHAN)   // 96 independent 512x512 images
#define H      512
#define W      512
#define PADT   10                 // top/bottom zero pad rows
#define HP     (H + 2 * PADT)     // 532 padded rows
#define WP     544                // padded width: 12 left zeros, 512 body, 20 right zeros
#define KS     21
#define KTAPS  (KS * KS)          // 441

// Two padded copies: B is A shifted left by one float (B[px] = A[px+1]).
__device__ float g_xpadA[(size_t)NIMG * HP * WP];
__device__ float g_xpadB[(size_t)NIMG * HP * WP];

typedef unsigned long long ull;

__device__ __forceinline__ void ffma2(ull& d, ull a, ull b) {
    asm("fma.rn.f32x2 %0, %1, %2, %0;" : "+l"(d) : "l"(a), "l"(b));
}

__device__ __forceinline__ void unpk(ull v, float& lo, float& hi) {
    asm("mov.b64 {%0, %1}, %2;" : "=f"(lo), "=f"(hi) : "l"(v));
}

// ---- kernel 1: build both padded copies -----------------------------------
// A[px] = x[gx] with px = gx + 12 (body px 12..523), py = gy + 10.
// B[px] = A[px+1].
__global__ void prepad_kernel(const float* __restrict__ x) {
    int idx = blockIdx.x * 256 + threadIdx.x;        // one quad per thread
    int q   = idx % (WP / 4);
    int ry  = idx / (WP / 4);                        // img*HP + py
    int py  = ry % HP;
    int img = ry / HP;
    bool rowok = (py >= PADT && py < PADT + H);
    const float* xrow = x + ((size_t)img * H + (py - PADT)) * W;

    float4 a = make_float4(0.f, 0.f, 0.f, 0.f);
    if (rowok && q >= 3 && q < 131)
        a = *reinterpret_cast<const float4*>(xrow + q * 4 - 12);

    float nxt = 0.f;
    if (rowok && q >= 2 && q <= 129)
        nxt = xrow[q * 4 - 8];                       // first elem of next quad

    float4 b = make_float4(a.y, a.z, a.w, nxt);

    *reinterpret_cast<float4*>(g_xpadA + (size_t)ry * WP + q * 4) = a;
    *reinterpret_cast<float4*>(g_xpadB + (size_t)ry * WP + q * 4) = b;
}

// ---- kernel 2: depthwise conv, row-pair packed FFMA2, MOV-free operands ---
// acc[c] = (out[Y][X+c], out[Y+1][X+c]).
// Fused tap table: kp[r][jj] = (k[r][jj-1], k[r-1][jj])  (out-of-range -> 0).
// acc[c] += pair(fl[o], fl[o+1]) * kp[r][jj],  o = c + jj + 1
//   even o=2m: pair = A-row 64-bit word m           (e[m], m in [1,14])
//   odd  o=2m+1: pair = B-row 64-bit word m         (ob[m], m in [0,14])
// CTA: 128 threads = 4 col-groups (8 cols) x 32 row-pairs (64 rows).
__global__ __launch_bounds__(128) void conv_kernel(const float* __restrict__ d_k,
                                                   float* __restrict__ d_out) {
    __shared__ float2 kp[22 * 22];

    const int tid = threadIdx.x;
    const int img = blockIdx.z;

    const float* kptr = d_k + (size_t)(img / NCHAN) * KTAPS;
    for (int i = tid; i < 22 * 22; i += 128) {
        int r  = i / 22;
        int jj = i % 22;
        float lo = (r <= 20 && jj >= 1) ? kptr[r * KS + jj - 1] : 0.f;
        float hi = (r >= 1 && jj <= 20) ? kptr[(r - 1) * KS + jj] : 0.f;
        kp[i] = make_float2(lo, hi);
    }
    __syncthreads();

    const int lane_x = tid & 3;
    const int pair_y = tid >> 2;
    const int X = blockIdx.x * 32 + lane_x * 8;
    const int Y = blockIdx.y * 64 + pair_y * 2;

    const size_t rowoff = ((size_t)img * HP + Y) * WP + X;
    const float* baseA = g_xpadA + rowoff;
    const float* baseB = g_xpadB + rowoff;

    ull acc[8];
#pragma unroll
    for (int c = 0; c < 8; ++c) acc[c] = 0ull;

#pragma unroll 2
    for (int r = 0; r < 22; ++r) {
        const ulonglong2* srcA =
            reinterpret_cast<const ulonglong2*>(baseA + (size_t)r * WP);
        const ulonglong2* srcB =
            reinterpret_cast<const ulonglong2*>(baseB + (size_t)r * WP);

        // 16 LDG.128: pairs arrive pre-aligned, no packing MOVs.
        ull e[16], ob[16];
#pragma unroll
        for (int j = 0; j < 8; ++j) {
            ulonglong2 ta = srcA[j];
            e[2 * j]     = ta.x;
            e[2 * j + 1] = ta.y;
        }
#pragma unroll
        for (int j = 0; j < 8; ++j) {
            ulonglong2 tb = srcB[j];
            ob[2 * j]     = tb.x;
            ob[2 * j + 1] = tb.y;
        }

        const ulonglong2* krow2 =
            reinterpret_cast<const ulonglong2*>(&kp[r * 22]);   // 176B row stride, 16B aligned
#pragma unroll
        for (int jh = 0; jh < 11; ++jh) {
            ulonglong2 kk2 = krow2[jh];                          // taps jj=2jh, 2jh+1
#pragma unroll
            for (int c = 0; c < 8; ++c) {
                const int o = c + 2 * jh + 1;
                ull a = (o & 1) ? ob[(o - 1) >> 1] : e[o >> 1];
                ffma2(acc[c], a, kk2.x);
            }
#pragma unroll
            for (int c = 0; c < 8; ++c) {
                const int o = c + 2 * jh + 2;
                ull a = (o & 1) ? ob[(o - 1) >> 1] : e[o >> 1];
                ffma2(acc[c], a, kk2.y);
            }
        }
    }

    float lo[8], hi[8];
#pragma unroll
    for (int c = 0; c < 8; ++c) unpk(acc[c], lo[c], hi[c]);

    float* outp = d_out + ((size_t)img * H + Y) * W + X;
    reinterpret_cast<float4*>(outp)[0]     = make_float4(lo[0], lo[1], lo[2], lo[3]);
    reinterpret_cast<float4*>(outp)[1]     = make_float4(lo[4], lo[5], lo[6], lo[7]);
    reinterpret_cast<float4*>(outp + W)[0] = make_float4(hi[0], hi[1], hi[2], hi[3]);
    reinterpret_cast<float4*>(outp + W)[1] = make_float4(hi[4], hi[5], hi[6], hi[7]);
}

// ---- launch ----------------------------------------------------------------
extern "C" void kernel_launch(void* const* d_in, const int* in_sizes, int n_in,
                              void* d_out, int out_size) {
    const float* x = (const float*)d_in[0];   // (32,3,512,512) fp32
    const float* k = (const float*)d_in[1];   // (32,1,21,21)  fp32
    float* out = (float*)d_out;

    const int total_quads = NIMG * HP * (WP / 4);    // 96*532*136
    prepad_kernel<<<total_quads / 256, 256>>>(x);

    dim3 grid(W / 32, H / 64, NIMG);                 // (16, 8, 96)
    conv_kernel<<<grid, 128>>>(k, out);
}

// round 4
// speedup vs baseline: 1.5721x; 1.5721x over previous
#include <cuda_runtime.h>

#define NCHAN  3
#define H      512
#define W      512
#define KS     21
#define KTAPS  (KS * KS)          // 441

// tile geometry: CTA = 32 output cols x 64 output rows, 128 threads = 4 warps
// warp w: output cols Xb + w*8 .. +7 ; lane py (0..31): output rows Yb+2py, Yb+2py+1
// input window: rows Yb-10 .. Yb+73 (84), cols Xb-12 .. Xb+43 (56 floats = 28 pairs)
#define TROWS  84
#define TPAIRS 32                 // padded pair-columns (swizzle needs 32 slots)
#define PLANE  (TROWS * TPAIRS)   // 2688 ull per plane

typedef unsigned long long ull;

__device__ __forceinline__ void ffma2(ull& d, ull a, ull b) {
    asm("fma.rn.f32x2 %0, %1, %2, %0;" : "+l"(d) : "l"(a), "l"(b));
}
__device__ __forceinline__ ull pk(float lo, float hi) {
    ull r; asm("mov.b64 %0, {%1, %2};" : "=l"(r) : "f"(lo), "f"(hi)); return r;
}
__device__ __forceinline__ void unpk(ull v, float& lo, float& hi) {
    asm("mov.b64 {%0, %1}, %2;" : "=f"(lo), "=f"(hi) : "l"(v));
}

// smPool[0..PLANE): plane A (pairs (fl[2m],fl[2m+1]))
// smPool[PLANE..2*PLANE): plane B (pairs (fl[2m+1],fl[2m+2]))
// pair p of row stored at slot p ^ ((row>>1)&15)
__global__ __launch_bounds__(128, 4) void conv_kernel(const float* __restrict__ x,
                                                      const float* __restrict__ d_k,
                                                      float* __restrict__ d_out) {
    __shared__ __align__(16) ull smPool[2 * PLANE];
    __shared__ __align__(16) float2 kp[22 * 22];

    const int tid = threadIdx.x;
    const int img = blockIdx.z;
    const int Xb  = blockIdx.x * 32;
    const int Yb  = blockIdx.y * 64;

    // fused diagonal tap table: kp[r][jj] = (k[r][jj-1], k[r-1][jj]); OOR -> 0
    const float* kptr = d_k + (size_t)(img / NCHAN) * KTAPS;
    for (int i = tid; i < 22 * 22; i += 128) {
        int r  = i / 22;
        int jj = i % 22;
        float lo = (r <= 20 && jj >= 1) ? kptr[r * KS + jj - 1] : 0.f;
        float hi = (r >= 1 && jj <= 20) ? kptr[(r - 1) * KS + jj] : 0.f;
        kp[i] = make_float2(lo, hi);
    }

    // ---- load input window into swizzled dual planes -----------------------
    const float* ximg = x + (size_t)img * H * W;
    for (int i = tid; i < TROWS * 14; i += 128) {
        int row = i / 14;                 // 0..83
        int q   = i % 14;                 // quad (4 floats) within 56-col window
        int gy  = Yb - 10 + row;
        int gx  = Xb - 12 + 4 * q;
        bool rok = ((unsigned)gy < H);
        float4 v = make_float4(0.f, 0.f, 0.f, 0.f);
        if (rok && gx >= 0 && gx <= W - 4)
            v = *reinterpret_cast<const float4*>(ximg + (size_t)gy * W + gx);
        float e4 = 0.f;
        int gx4 = gx + 4;
        if (rok && gx4 >= 0 && gx4 < W)
            e4 = ximg[(size_t)gy * W + gx4];

        int sw   = (row >> 1) & 15;
        int base = (2 * q) ^ (sw & 14);   // even slot base; halves swap if sw odd
        ull alo = pk(v.x, v.y), ahi = pk(v.z, v.w);
        ull blo = pk(v.y, v.z), bhi = pk(v.w, e4);
        if (sw & 1) { ull t = alo; alo = ahi; ahi = t; t = blo; blo = bhi; bhi = t; }
        ull* arow = smPool + row * TPAIRS;
        *reinterpret_cast<ulonglong2*>(arow + base)         = make_ulonglong2(alo, ahi);
        *reinterpret_cast<ulonglong2*>(arow + PLANE + base) = make_ulonglong2(blo, bhi);
    }
    __syncthreads();

    // ---- main loop ----------------------------------------------------------
    const int wq = tid >> 5;          // warp = col group
    const int py = tid & 31;          // row pair
    const int w4 = wq * 4;            // pair-column base for this thread

    ull acc[8];
#pragma unroll
    for (int c = 0; c < 8; ++c) acc[c] = 0ull;

#pragma unroll 1
    for (int r2 = 0; r2 < 11; ++r2) {
        const int sw = (py + r2) & 15;                    // shared by the row pair
        const ull* Arow = smPool + (2 * py + 2 * r2) * TPAIRS;

        int idx[15];
#pragma unroll
        for (int m = 0; m < 15; ++m) idx[m] = (w4 + m) ^ sw;

        // ---- row 0 of the pair (r = 2*r2) ----
        ull e0[15], b0[15];
#pragma unroll
        for (int m = 0; m < 15; ++m) b0[m] = Arow[PLANE + idx[m]];
#pragma unroll
        for (int m = 1; m < 15; ++m) e0[m] = Arow[idx[m]];

        const ulonglong2* k0 =
            reinterpret_cast<const ulonglong2*>(kp + (2 * r2) * 22);
#pragma unroll
        for (int jh = 0; jh < 11; ++jh) {
            ulonglong2 kk = k0[jh];
#pragma unroll
            for (int c = 0; c < 8; ++c) {                 // jj = 2jh, o = c+2jh+1
                ull a = (c & 1) ? e0[jh + (c + 1) / 2] : b0[jh + c / 2];
                ffma2(acc[c], a, kk.x);
            }
#pragma unroll
            for (int c = 0; c < 8; ++c) {                 // jj = 2jh+1, o = c+2jh+2
                ull a = (c & 1) ? b0[jh + (c + 1) / 2] : e0[jh + c / 2 + 1];
                ffma2(acc[c], a, kk.y);
            }
        }

        // ---- row 1 of the pair (r = 2*r2+1), same swizzle ----
        ull e1[15], b1[15];
#pragma unroll
        for (int m = 0; m < 15; ++m) b1[m] = Arow[PLANE + TPAIRS + idx[m]];
#pragma unroll
        for (int m = 1; m < 15; ++m) e1[m] = Arow[TPAIRS + idx[m]];

        const ulonglong2* k1 =
            reinterpret_cast<const ulonglong2*>(kp + (2 * r2 + 1) * 22);
#pragma unroll
        for (int jh = 0; jh < 11; ++jh) {
            ulonglong2 kk = k1[jh];
#pragma unroll
            for (int c = 0; c < 8; ++c) {
                ull a = (c & 1) ? e1[jh + (c + 1) / 2] : b1[jh + c / 2];
                ffma2(acc[c], a, kk.x);
            }
#pragma unroll
            for (int c = 0; c < 8; ++c) {
                ull a = (c & 1) ? b1[jh + (c + 1) / 2] : e1[jh + c / 2 + 1];
                ffma2(acc[c], a, kk.y);
            }
        }
    }

    // ---- store: lane-lo -> row Y, lane-hi -> row Y+1 ------------------------
    float lo[8], hi[8];
#pragma unroll
    for (int c = 0; c < 8; ++c) unpk(acc[c], lo[c], hi[c]);

    float* op = d_out + ((size_t)img * H + Yb + 2 * py) * W + Xb + wq * 8;
    reinterpret_cast<float4*>(op)[0]     = make_float4(lo[0], lo[1], lo[2], lo[3]);
    reinterpret_cast<float4*>(op)[1]     = make_float4(lo[4], lo[5], lo[6], lo[7]);
    reinterpret_cast<float4*>(op + W)[0] = make_float4(hi[0], hi[1], hi[2], hi[3]);
    reinterpret_cast<float4*>(op + W)[1] = make_float4(hi[4], hi[5], hi[6], hi[7]);
}

extern "C" void kernel_launch(void* const* d_in, const int* in_sizes, int n_in,
                              void* d_out, int out_size) {
    const float* x = (const float*)d_in[0];   // (32,3,512,512) fp32
    const float* k = (const float*)d_in[1];   // (32,1,21,21)  fp32
    float* out = (float*)d_out;

    dim3 grid(W / 32, H / 64, 96);            // (16, 8, 96)
    conv_kernel<<<grid, 128>>>(x, k, out);
}

// round 5
// speedup vs baseline: 1.7427x; 1.1085x over previous
#include <cuda_runtime.h>

#define NCHAN  3
#define H      512
#define W      512
#define KS     21
#define KTAPS  (KS * KS)          // 441

// CTA tile: 64 output cols x 64 output rows, 128 threads = 4 warps.
// thread = (colg, py): colg 0..3 -> 16 cols each; py 0..31 -> rows Yb+2py, +2py+1.
// Input window: rows Yb-10..Yb+73 (84), cols Xb-12..Xb+76 (89 floats, 44 pairs).
#define TROWS  84
#define TPAIRS 48                 // 44 pairs padded for XOR swizzle (max slot 47)
#define PLANE  (TROWS * TPAIRS)   // 4032 ull per plane

typedef unsigned long long ull;

__device__ __forceinline__ void ffma2(ull& d, ull a, ull b) {
    asm("fma.rn.f32x2 %0, %1, %2, %0;" : "+l"(d) : "l"(a), "l"(b));
}
__device__ __forceinline__ ull pk(float lo, float hi) {
    ull r; asm("mov.b64 %0, {%1, %2};" : "=l"(r) : "f"(lo), "f"(hi)); return r;
}
__device__ __forceinline__ void unpk(ull v, float& lo, float& hi) {
    asm("mov.b64 {%0, %1}, %2;" : "=f"(lo), "=f"(hi) : "l"(v));
}

// dynamic smem layout: [A plane: PLANE ull][B plane: PLANE ull][kp: 484 float2]
#define SMEM_BYTES (2 * PLANE * 8 + 22 * 22 * 8)

__global__ __launch_bounds__(128, 3) void conv_kernel(const float* __restrict__ x,
                                                      const float* __restrict__ d_k,
                                                      float* __restrict__ d_out) {
    extern __shared__ __align__(16) ull sm[];
    ull* smA = sm;
    ull* smB = sm + PLANE;
    float2* kp = reinterpret_cast<float2*>(sm + 2 * PLANE);

    const int tid = threadIdx.x;
    const int img = blockIdx.z;
    const int Xb  = blockIdx.x * 64;
    const int Yb  = blockIdx.y * 64;

    // fused diagonal tap table: kp[r][jj] = (k[r][jj-1], k[r-1][jj]); OOR -> 0
    const float* kptr = d_k + (size_t)(img / NCHAN) * KTAPS;
    for (int i = tid; i < 22 * 22; i += 128) {
        int r  = i / 22;
        int jj = i % 22;
        float lo = (r <= 20 && jj >= 1) ? kptr[r * KS + jj - 1] : 0.f;
        float hi = (r >= 1 && jj <= 20) ? kptr[(r - 1) * KS + jj] : 0.f;
        kp[i] = make_float2(lo, hi);
    }

    // ---- load window into dual swizzled planes (even-only XOR swizzle) ----
    const float* ximg = x + (size_t)img * H * W;
    for (int i = tid; i < TROWS * 22; i += 128) {
        int row = i / 22;                  // 0..83
        int q   = i % 22;                  // quad within 88-float window
        int gy  = Yb - 10 + row;
        int gx  = Xb - 12 + 4 * q;
        bool rok = ((unsigned)gy < H);
        float4 v = make_float4(0.f, 0.f, 0.f, 0.f);
        if (rok && gx >= 0 && gx <= W - 4)
            v = *reinterpret_cast<const float4*>(ximg + (size_t)gy * W + gx);
        float e4 = 0.f;
        int gx4 = gx + 4;
        if (rok && gx4 >= 0 && gx4 < W)
            e4 = ximg[(size_t)gy * W + gx4];

        int sw2  = ((row >> 1) & 7) << 1;
        int base = (2 * q) ^ sw2;          // even slot; pair (base, base+1)
        ull* arow = smA + row * TPAIRS;
        ull* brow = smB + row * TPAIRS;
        *reinterpret_cast<ulonglong2*>(arow + base) =
            make_ulonglong2(pk(v.x, v.y), pk(v.z, v.w));
        *reinterpret_cast<ulonglong2*>(brow + base) =
            make_ulonglong2(pk(v.y, v.z), pk(v.w, e4));
    }
    __syncthreads();

    // ---- main loop: 16 cols x 2 rows per thread ----------------------------
    const int colg = tid >> 5;            // 4 col groups of 16
    const int py   = tid & 31;            // row pair
    const int p0   = colg * 8;            // global pair base for this thread

    ull acc[16];
#pragma unroll
    for (int c = 0; c < 16; ++c) acc[c] = 0ull;

#pragma unroll 1
    for (int r2 = 0; r2 < 11; ++r2) {
        const int sw2 = (((py + r2) & 7) << 1);   // shared by both rows of pair
        const int rowi = 2 * py + 2 * r2;

        // ---- row 0 ----
        {
            const ull* Ar = smA + rowi * TPAIRS;
            const ull* Br = smB + rowi * TPAIRS;
            ull e[20], b[20];
#pragma unroll
            for (int t = 0; t < 10; ++t) {
                int s = (p0 + 2 * t) ^ sw2;
                ulonglong2 va = *reinterpret_cast<const ulonglong2*>(Ar + s);
                ulonglong2 vb = *reinterpret_cast<const ulonglong2*>(Br + s);
                e[2 * t] = va.x; e[2 * t + 1] = va.y;
                b[2 * t] = vb.x; b[2 * t + 1] = vb.y;
            }
            const ulonglong2* k0 =
                reinterpret_cast<const ulonglong2*>(kp + (2 * r2) * 22);
#pragma unroll
            for (int jh = 0; jh < 11; ++jh) {
                ulonglong2 kk = k0[jh];
#pragma unroll
                for (int c = 0; c < 16; ++c) {            // jj = 2jh
                    ull a = (c & 1) ? e[jh + (c + 1) / 2] : b[jh + c / 2];
                    ffma2(acc[c], a, kk.x);
                }
#pragma unroll
                for (int c = 0; c < 16; ++c) {            // jj = 2jh+1
                    ull a = (c & 1) ? b[jh + (c + 1) / 2] : e[jh + c / 2 + 1];
                    ffma2(acc[c], a, kk.y);
                }
            }
        }
        // ---- row 1 (same swizzle: (rowi+1)>>1 == py+r2) ----
        {
            const ull* Ar = smA + (rowi + 1) * TPAIRS;
            const ull* Br = smB + (rowi + 1) * TPAIRS;
            ull e[20], b[20];
#pragma unroll
            for (int t = 0; t < 10; ++t) {
                int s = (p0 + 2 * t) ^ sw2;
                ulonglong2 va = *reinterpret_cast<const ulonglong2*>(Ar + s);
                ulonglong2 vb = *reinterpret_cast<const ulonglong2*>(Br + s);
                e[2 * t] = va.x; e[2 * t + 1] = va.y;
                b[2 * t] = vb.x; b[2 * t + 1] = vb.y;
            }
            const ulonglong2* k1 =
                reinterpret_cast<const ulonglong2*>(kp + (2 * r2 + 1) * 22);
#pragma unroll
            for (int jh = 0; jh < 11; ++jh) {
                ulonglong2 kk = k1[jh];
#pragma unroll
                for (int c = 0; c < 16; ++c) {
                    ull a = (c & 1) ? e[jh + (c + 1) / 2] : b[jh + c / 2];
                    ffma2(acc[c], a, kk.x);
                }
#pragma unroll
                for (int c = 0; c < 16; ++c) {
                    ull a = (c & 1) ? b[jh + (c + 1) / 2] : e[jh + c / 2 + 1];
                    ffma2(acc[c], a, kk.y);
                }
            }
        }
    }

    // ---- store: 2 rows x 16 cols ------------------------------------------
    float lo[16], hi[16];
#pragma unroll
    for (int c = 0; c < 16; ++c) unpk(acc[c], lo[c], hi[c]);

    float* op = d_out + ((size_t)img * H + Yb + 2 * py) * W + Xb + colg * 16;
#pragma unroll
    for (int j = 0; j < 4; ++j) {
        reinterpret_cast<float4*>(op)[j] =
            make_float4(lo[4 * j], lo[4 * j + 1], lo[4 * j + 2], lo[4 * j + 3]);
        reinterpret_cast<float4*>(op + W)[j] =
            make_float4(hi[4 * j], hi[4 * j + 1], hi[4 * j + 2], hi[4 * j + 3]);
    }
}

extern "C" void kernel_launch(void* const* d_in, const int* in_sizes, int n_in,
                              void* d_out, int out_size) {
    const float* x = (const float*)d_in[0];   // (32,3,512,512) fp32
    const float* k = (const float*)d_in[1];   // (32,1,21,21)  fp32
    float* out = (float*)d_out;

    cudaFuncSetAttribute(conv_kernel,
                         cudaFuncAttributeMaxDynamicSharedMemorySize, SMEM_BYTES);

    dim3 grid(W / 64, H / 64, 96);            // (8, 8, 96)
    conv_kernel<<<grid, 128, SMEM_BYTES>>>(x, k, out);
}